// round 1
// baseline (speedup 1.0000x reference)
#include <cuda_runtime.h>

// Problem constants
#define NPTS 4096
#define CH   512
#define OUTF 256
#define KTOP 4
#define EPSV 1e-5f

// ---------------- scratch (static device globals; no allocation) ----------------
__device__ float g_si[(size_t)NPTS * NPTS];   // 64 MB similarity matrix
__device__ float g_u [(size_t)NPTS * CH];     // x @ U_w^T + U_b
__device__ float g_v [(size_t)NPTS * CH];     // x @ V_w^T + V_b
__device__ float g_h [(size_t)NPTS * CH];     // post-norm activations
__device__ float g_dinv[NPTS];                // deg^-1/2 per row
__device__ int   g_deg [NPTS];
__device__ int   g_idx [NPTS * 16];           // neighbor indices (cap 16)

// ---------------- shared GEMM core: 128x128 tile, BK=16, 8x8 per thread ----------
// A [M,Kd] row-major, B [Ncols,Kd] row-major; computes acc = A_tile * B_tile^T
__device__ __forceinline__ void gemm_core(const float* __restrict__ A,
                                          const float* __restrict__ B,
                                          int Kd, int m0, int n0,
                                          float acc[8][8])
{
    __shared__ float As[16][128];
    __shared__ float Bs[16][128];
    const int tid = threadIdx.x;
    const int tx  = tid & 15;
    const int ty  = tid >> 4;
    const int lr  = tid >> 2;        // 0..63
    const int lc  = (tid & 3) * 4;   // 0,4,8,12

#pragma unroll
    for (int i = 0; i < 8; i++)
#pragma unroll
        for (int j = 0; j < 8; j++) acc[i][j] = 0.f;

    for (int k0 = 0; k0 < Kd; k0 += 16) {
#pragma unroll
        for (int h = 0; h < 2; h++) {
            int r = lr + h * 64;
            float4 va = *(const float4*)(A + (size_t)(m0 + r) * Kd + k0 + lc);
            As[lc + 0][r] = va.x; As[lc + 1][r] = va.y;
            As[lc + 2][r] = va.z; As[lc + 3][r] = va.w;
            float4 vb = *(const float4*)(B + (size_t)(n0 + r) * Kd + k0 + lc);
            Bs[lc + 0][r] = vb.x; Bs[lc + 1][r] = vb.y;
            Bs[lc + 2][r] = vb.z; Bs[lc + 3][r] = vb.w;
        }
        __syncthreads();
#pragma unroll
        for (int k = 0; k < 16; k++) {
            float4 a0 = *(const float4*)&As[k][ty * 8];
            float4 a1 = *(const float4*)&As[k][ty * 8 + 4];
            float4 b0 = *(const float4*)&Bs[k][tx * 8];
            float4 b1 = *(const float4*)&Bs[k][tx * 8 + 4];
            float a[8] = {a0.x, a0.y, a0.z, a0.w, a1.x, a1.y, a1.z, a1.w};
            float b[8] = {b0.x, b0.y, b0.z, b0.w, b1.x, b1.y, b1.z, b1.w};
#pragma unroll
            for (int i = 0; i < 8; i++)
#pragma unroll
                for (int j = 0; j < 8; j++)
                    acc[i][j] = fmaf(a[i], b[j], acc[i][j]);
        }
        __syncthreads();
    }
}

// ---------------- K1: si = x @ x^T, upper-triangular tiles + mirror ----------------
__global__ __launch_bounds__(256) void si_gemm(const float* __restrict__ X)
{
    const int bj = blockIdx.x;   // column tile
    const int bi = blockIdx.y;   // row tile
    if (bi > bj) return;
    const int m0 = bi * 128, n0 = bj * 128;
    float acc[8][8];
    gemm_core(X, X, CH, m0, n0, acc);

    const int tx = threadIdx.x & 15, ty = threadIdx.x >> 4;
#pragma unroll
    for (int i = 0; i < 8; i++) {
        int m = m0 + ty * 8 + i;
#pragma unroll
        for (int j = 0; j < 8; j += 4) {
            int n = n0 + tx * 8 + j;
            float4 o = make_float4(acc[i][j], acc[i][j + 1], acc[i][j + 2], acc[i][j + 3]);
            *(float4*)(g_si + (size_t)m * NPTS + n) = o;
        }
    }
    if (bi != bj) {
#pragma unroll
        for (int i = 0; i < 8; i++) {
            int m = m0 + ty * 8 + i;
#pragma unroll
            for (int j = 0; j < 8; j++) {
                int n = n0 + tx * 8 + j;
                g_si[(size_t)n * NPTS + m] = acc[i][j];
            }
        }
    }
}

// ---------------- K2: per-row top-4 threshold + neighbor collection ----------------
__device__ __forceinline__ void ins4(float& v0, float& v1, float& v2, float& v3, float x)
{
    if (x > v3) {
        if (x > v1) {
            if (x > v0) { v3 = v2; v2 = v1; v1 = v0; v0 = x; }
            else        { v3 = v2; v2 = v1; v1 = x; }
        } else {
            if (x > v2) { v3 = v2; v2 = x; }
            else        { v3 = x; }
        }
    }
}

__global__ __launch_bounds__(256) void topk_kernel()
{
    const int row = blockIdx.x;
    const int tid = threadIdx.x;
    const float* __restrict__ s = g_si + (size_t)row * NPTS;

    float v0 = -1e30f, v1 = -1e30f, v2 = -1e30f, v3 = -1e30f;
    for (int j = tid; j < NPTS; j += 256) ins4(v0, v1, v2, v3, s[j]);

    __shared__ float sv[256][4];
    sv[tid][0] = v0; sv[tid][1] = v1; sv[tid][2] = v2; sv[tid][3] = v3;
    __syncthreads();
    for (int st = 128; st > 0; st >>= 1) {
        if (tid < st) {
            float a0 = sv[tid][0], a1 = sv[tid][1], a2 = sv[tid][2], a3 = sv[tid][3];
            ins4(a0, a1, a2, a3, sv[tid + st][0]);
            ins4(a0, a1, a2, a3, sv[tid + st][1]);
            ins4(a0, a1, a2, a3, sv[tid + st][2]);
            ins4(a0, a1, a2, a3, sv[tid + st][3]);
            sv[tid][0] = a0; sv[tid][1] = a1; sv[tid][2] = a2; sv[tid][3] = a3;
        }
        __syncthreads();
    }

    __shared__ float thr_s;
    __shared__ int cnt;
    if (tid == 0) { thr_s = sv[0][3]; cnt = 0; }
    __syncthreads();
    const float thr = thr_s;
    for (int j = tid; j < NPTS; j += 256) {
        if (s[j] >= thr) {
            int p = atomicAdd(&cnt, 1);
            if (p < 16) g_idx[row * 16 + p] = j;
        }
    }
    __syncthreads();
    if (tid == 0) {
        g_deg[row]  = min(cnt, 16);
        g_dinv[row] = rsqrtf((float)cnt);
    }
}

// ---------------- K3: u/v projections (one kernel, z-dim selects U vs V) ----------
__global__ __launch_bounds__(256) void uv_gemm(const float* __restrict__ X,
                                               const float* __restrict__ Uw,
                                               const float* __restrict__ Ub,
                                               const float* __restrict__ Vw,
                                               const float* __restrict__ Vb)
{
    const bool isV = (blockIdx.z == 1);
    const float* W    = isV ? Vw : Uw;
    const float* bias = isV ? Vb : Ub;
    float* Co         = isV ? g_v : g_u;
    const int m0 = blockIdx.y * 128, n0 = blockIdx.x * 128;
    float acc[8][8];
    gemm_core(X, W, CH, m0, n0, acc);
    const int tx = threadIdx.x & 15, ty = threadIdx.x >> 4;
#pragma unroll
    for (int i = 0; i < 8; i++) {
        int m = m0 + ty * 8 + i;
#pragma unroll
        for (int j = 0; j < 8; j += 4) {
            int n = n0 + tx * 8 + j;
            float4 o = make_float4(acc[i][j]     + bias[n],
                                   acc[i][j + 1] + bias[n + 1],
                                   acc[i][j + 2] + bias[n + 2],
                                   acc[i][j + 3] + bias[n + 3]);
            *(float4*)(Co + (size_t)m * CH + n) = o;
        }
    }
}

// ---------------- K4: sparse aggregate + per-row norm + relu -> h ------------------
__global__ __launch_bounds__(128) void combine_kernel(const float* __restrict__ X)
{
    const int row = blockIdx.x, tid = threadIdx.x;
    __shared__ int   nidx[16];
    __shared__ float nw[16];
    __shared__ float red[128];
    __shared__ float mean_s, inv_s;

    const int   deg = g_deg[row];
    const float di  = g_dinv[row];
    if (tid < deg) {
        int j = g_idx[row * 16 + tid];
        nidx[tid] = j;
        nw[tid]   = di * g_dinv[j];
    }
    __syncthreads();

    float z[4];
#pragma unroll
    for (int q = 0; q < 4; q++) {
        int c = q * 128 + tid;
        float a = g_u[(size_t)row * CH + c];
        for (int t = 0; t < deg; t++)
            a = fmaf(nw[t], g_v[(size_t)nidx[t] * CH + c], a);
        z[q] = a;
    }

    // mean
    red[tid] = z[0] + z[1] + z[2] + z[3];
    __syncthreads();
    for (int st = 64; st > 0; st >>= 1) { if (tid < st) red[tid] += red[tid + st]; __syncthreads(); }
    if (tid == 0) mean_s = red[0] * (1.f / CH);
    __syncthreads();
    const float mean = mean_s;

    // biased variance (two-pass)
    float vs = 0.f;
#pragma unroll
    for (int q = 0; q < 4; q++) { float d = z[q] - mean; vs += d * d; }
    red[tid] = vs;
    __syncthreads();
    for (int st = 64; st > 0; st >>= 1) { if (tid < st) red[tid] += red[tid + st]; __syncthreads(); }
    if (tid == 0) inv_s = rsqrtf(red[0] * (1.f / CH) + EPSV);
    __syncthreads();
    const float inv = inv_s;

#pragma unroll
    for (int q = 0; q < 4; q++) {
        int c = q * 128 + tid;
        float h = X[(size_t)row * CH + c] + (z[q] - mean) * inv;
        g_h[(size_t)row * CH + c] = fmaxf(h, 0.f);
    }
}

// ---------------- K5: out = h @ fc_w^T + fc_b --------------------------------------
__global__ __launch_bounds__(256) void fc_gemm(const float* __restrict__ Fw,
                                               const float* __restrict__ Fb,
                                               float* __restrict__ out)
{
    const int m0 = blockIdx.y * 128, n0 = blockIdx.x * 128;
    float acc[8][8];
    gemm_core(g_h, Fw, CH, m0, n0, acc);
    const int tx = threadIdx.x & 15, ty = threadIdx.x >> 4;
#pragma unroll
    for (int i = 0; i < 8; i++) {
        int m = m0 + ty * 8 + i;
#pragma unroll
        for (int j = 0; j < 8; j += 4) {
            int n = n0 + tx * 8 + j;
            float4 o = make_float4(acc[i][j]     + Fb[n],
                                   acc[i][j + 1] + Fb[n + 1],
                                   acc[i][j + 2] + Fb[n + 2],
                                   acc[i][j + 3] + Fb[n + 3]);
            *(float4*)(out + (size_t)m * OUTF + n) = o;
        }
    }
}

// ---------------- launch ----------------
extern "C" void kernel_launch(void* const* d_in, const int* in_sizes, int n_in,
                              void* d_out, int out_size)
{
    const float* x  = (const float*)d_in[0];
    const float* Uw = (const float*)d_in[1];
    const float* Ub = (const float*)d_in[2];
    const float* Vw = (const float*)d_in[3];
    const float* Vb = (const float*)d_in[4];
    const float* Fw = (const float*)d_in[5];
    const float* Fb = (const float*)d_in[6];
    float* out = (float*)d_out;

    // K1: similarity matrix (upper triangular + mirror)
    si_gemm<<<dim3(32, 32), 256>>>(x);
    // K2: per-row top-4 threshold, neighbor list, degrees
    topk_kernel<<<NPTS, 256>>>();
    // K3: u and v projections
    uv_gemm<<<dim3(4, 32, 2), 256>>>(x, Uw, Ub, Vw, Vb);
    // K4: sparse A@v + u, per-row batchnorm stats, relu
    combine_kernel<<<NPTS, 128>>>(x);
    // K5: final fc
    fc_gemm<<<dim3(2, 32), 256>>>(Fw, Fb, out);
}

// round 2
// speedup vs baseline: 1.5780x; 1.5780x over previous
#include <cuda_runtime.h>
#include <cuda_bf16.h>
#include <cstdint>

#define NPTS 4096
#define CH   512
#define OUTF 256
#define EPSV 1e-5f
#define SA   40   // smem k-stride (bf16 elems) for 128x32 tiles, padded vs 32 to kill bank conflicts

// ---------------- scratch ----------------
__device__ __nv_bfloat16 g_sib[(size_t)NPTS * NPTS];  // 32 MB approximate similarity
__device__ float g_u [(size_t)NPTS * CH];
__device__ float g_v [(size_t)NPTS * CH];
__device__ float g_h [(size_t)NPTS * CH];
__device__ float g_dinv[NPTS];
__device__ int   g_deg [NPTS];
__device__ int   g_idx [NPTS * 16];

// ================= K1: approximate si = x@x.T in bf16 tensor cores =================
__device__ __forceinline__ void mma16816(float c[4], const uint32_t a[4], const uint32_t b[2])
{
    asm volatile(
        "mma.sync.aligned.m16n8k16.row.col.f32.bf16.bf16.f32 "
        "{%0,%1,%2,%3}, {%4,%5,%6,%7}, {%8,%9}, {%0,%1,%2,%3};"
        : "+f"(c[0]), "+f"(c[1]), "+f"(c[2]), "+f"(c[3])
        : "r"(a[0]), "r"(a[1]), "r"(a[2]), "r"(a[3]), "r"(b[0]), "r"(b[1]));
}

__global__ __launch_bounds__(256) void si_mma(const float* __restrict__ X)
{
    const int bj = blockIdx.x, bi = blockIdx.y;
    if (bi > bj) return;
    const int m0 = bi * 128, n0 = bj * 128;

    __shared__ __nv_bfloat16 As[128 * SA];
    __shared__ __nv_bfloat16 Bs[128 * SA];

    const int tid  = threadIdx.x;
    const int warp = tid >> 5, lane = tid & 31;
    const int wm = warp & 3;        // 4 warps along m (32 rows each)
    const int wn = warp >> 2;       // 2 warps along n (64 cols each)
    const int grp = lane >> 2, qd = lane & 3;

    float acc[2][8][4];
#pragma unroll
    for (int mi = 0; mi < 2; mi++)
#pragma unroll
        for (int ni = 0; ni < 8; ni++)
#pragma unroll
            for (int e = 0; e < 4; e++) acc[mi][ni][e] = 0.f;

    const int lr = tid >> 3;            // 0..31
    const int lc = (tid & 7) * 4;       // 0..28

    for (int k0 = 0; k0 < CH; k0 += 32) {
#pragma unroll
        for (int p = 0; p < 4; p++) {
            int rr = lr + p * 32;
            float4 va = *(const float4*)(X + (size_t)(m0 + rr) * CH + k0 + lc);
            *(__nv_bfloat162*)&As[rr * SA + lc]     = __floats2bfloat162_rn(va.x, va.y);
            *(__nv_bfloat162*)&As[rr * SA + lc + 2] = __floats2bfloat162_rn(va.z, va.w);
            float4 vb = *(const float4*)(X + (size_t)(n0 + rr) * CH + k0 + lc);
            *(__nv_bfloat162*)&Bs[rr * SA + lc]     = __floats2bfloat162_rn(vb.x, vb.y);
            *(__nv_bfloat162*)&Bs[rr * SA + lc + 2] = __floats2bfloat162_rn(vb.z, vb.w);
        }
        __syncthreads();
#pragma unroll
        for (int kk = 0; kk < 32; kk += 16) {
            uint32_t afr[2][4], bfr[8][2];
#pragma unroll
            for (int mi = 0; mi < 2; mi++) {
                int row = wm * 32 + mi * 16 + grp;
                afr[mi][0] = *(const uint32_t*)&As[row * SA + kk + qd * 2];
                afr[mi][1] = *(const uint32_t*)&As[(row + 8) * SA + kk + qd * 2];
                afr[mi][2] = *(const uint32_t*)&As[row * SA + kk + qd * 2 + 8];
                afr[mi][3] = *(const uint32_t*)&As[(row + 8) * SA + kk + qd * 2 + 8];
            }
#pragma unroll
            for (int ni = 0; ni < 8; ni++) {
                int col = wn * 64 + ni * 8 + grp;
                bfr[ni][0] = *(const uint32_t*)&Bs[col * SA + kk + qd * 2];
                bfr[ni][1] = *(const uint32_t*)&Bs[col * SA + kk + qd * 2 + 8];
            }
#pragma unroll
            for (int mi = 0; mi < 2; mi++)
#pragma unroll
                for (int ni = 0; ni < 8; ni++)
                    mma16816(acc[mi][ni], afr[mi], bfr[ni]);
        }
        __syncthreads();
    }

    // epilogue: bf16 store (upper tile) + mirror
#pragma unroll
    for (int mi = 0; mi < 2; mi++) {
        int m = m0 + wm * 32 + mi * 16 + grp;
#pragma unroll
        for (int ni = 0; ni < 8; ni++) {
            int n = n0 + wn * 64 + ni * 8 + qd * 2;
            float c0 = acc[mi][ni][0], c1 = acc[mi][ni][1];
            float c2 = acc[mi][ni][2], c3 = acc[mi][ni][3];
            *(__nv_bfloat162*)&g_sib[(size_t)m * NPTS + n]       = __floats2bfloat162_rn(c0, c1);
            *(__nv_bfloat162*)&g_sib[(size_t)(m + 8) * NPTS + n] = __floats2bfloat162_rn(c2, c3);
            if (bi != bj) {
                g_sib[(size_t)n * NPTS + m]           = __float2bfloat16_rn(c0);
                g_sib[(size_t)(n + 1) * NPTS + m]     = __float2bfloat16_rn(c1);
                g_sib[(size_t)n * NPTS + m + 8]       = __float2bfloat16_rn(c2);
                g_sib[(size_t)(n + 1) * NPTS + m + 8] = __float2bfloat16_rn(c3);
            }
        }
    }
}

// ================= K2: approx top-8 candidates + fp32 exact refine =================
__device__ __forceinline__ void ins8(float v[8], float x)
{
    if (x > v[7]) {
        v[7] = x;
#pragma unroll
        for (int i = 7; i > 0; i--) {
            if (v[i] > v[i - 1]) { float t = v[i]; v[i] = v[i - 1]; v[i - 1] = t; }
        }
    }
}

__global__ __launch_bounds__(256) void topk_refine(const float* __restrict__ X)
{
    const int row = blockIdx.x;
    const int tid = threadIdx.x;
    const int warp = tid >> 5, lane = tid & 31;
    const __nv_bfloat16* __restrict__ s = g_sib + (size_t)row * NPTS;

    __shared__ float sv[256][8];
    __shared__ float xr[CH];
    __shared__ float ex[32];
    __shared__ int   cand[32];
    __shared__ int   cnt;
    __shared__ float thr8_s;

    // stage x[row] into smem; init cnt
    xr[tid]       = X[(size_t)row * CH + tid];
    xr[tid + 256] = X[(size_t)row * CH + tid + 256];
    if (tid == 0) cnt = 0;

    // per-thread top-8 over approximate row
    float v[8];
#pragma unroll
    for (int i = 0; i < 8; i++) v[i] = -1e30f;
    for (int j = tid; j < NPTS; j += 256) ins8(v, __bfloat162float(s[j]));
#pragma unroll
    for (int i = 0; i < 8; i++) sv[tid][i] = v[i];
    __syncthreads();
    for (int st = 128; st > 0; st >>= 1) {
        if (tid < st) {
#pragma unroll
            for (int i = 0; i < 8; i++) ins8(v, sv[tid + st][i]);
#pragma unroll
            for (int i = 0; i < 8; i++) sv[tid][i] = v[i];
        }
        __syncthreads();
    }
    if (tid == 0) thr8_s = sv[0][7];
    __syncthreads();
    const float thr8 = thr8_s;

    // collect candidate indices (approx >= approx-8th). >=8 guaranteed; cap 32.
    for (int j = tid; j < NPTS; j += 256) {
        if (__bfloat162float(s[j]) >= thr8) {
            int p = atomicAdd(&cnt, 1);
            if (p < 32) cand[p] = j;
        }
    }
    __syncthreads();
    const int cn = min(cnt, 32);

    // exact fp32 dot for each candidate (warp per candidate)
    for (int c = warp; c < cn; c += 8) {
        const float* __restrict__ xc = X + (size_t)cand[c] * CH;
        float sum = 0.f;
        for (int k = lane; k < CH; k += 32) sum = fmaf(xr[k], xc[k], sum);
#pragma unroll
        for (int o = 16; o > 0; o >>= 1) sum += __shfl_xor_sync(0xffffffffu, sum, o);
        if (lane == 0) ex[c] = sum;
    }
    __syncthreads();

    // exact top-4 threshold, degree, neighbor list
    if (tid == 0) {
        float tmp[32];
        for (int c = 0; c < cn; c++) tmp[c] = ex[c];
        float thr = -1e30f;
        for (int p = 0; p < 4; p++) {
            int bidx = 0; float bv = -1e30f;
            for (int c = 0; c < cn; c++) if (tmp[c] > bv) { bv = tmp[c]; bidx = c; }
            thr = bv; tmp[bidx] = -1e30f;
        }
        int d = 0;
        for (int c = 0; c < cn; c++) {
            if (ex[c] >= thr) { if (d < 16) g_idx[row * 16 + d] = cand[c]; d++; }
        }
        g_deg[row]  = min(d, 16);
        g_dinv[row] = rsqrtf((float)d);
    }
}

// ================= fp32 GEMM core (unchanged) for uv / fc =================
__device__ __forceinline__ void gemm_core(const float* __restrict__ A,
                                          const float* __restrict__ B,
                                          int Kd, int m0, int n0,
                                          float acc[8][8])
{
    __shared__ float As[16][128];
    __shared__ float Bs[16][128];
    const int tid = threadIdx.x;
    const int tx  = tid & 15;
    const int ty  = tid >> 4;
    const int lr  = tid >> 2;
    const int lc  = (tid & 3) * 4;

#pragma unroll
    for (int i = 0; i < 8; i++)
#pragma unroll
        for (int j = 0; j < 8; j++) acc[i][j] = 0.f;

    for (int k0 = 0; k0 < Kd; k0 += 16) {
#pragma unroll
        for (int h = 0; h < 2; h++) {
            int r = lr + h * 64;
            float4 va = *(const float4*)(A + (size_t)(m0 + r) * Kd + k0 + lc);
            As[lc + 0][r] = va.x; As[lc + 1][r] = va.y;
            As[lc + 2][r] = va.z; As[lc + 3][r] = va.w;
            float4 vb = *(const float4*)(B + (size_t)(n0 + r) * Kd + k0 + lc);
            Bs[lc + 0][r] = vb.x; Bs[lc + 1][r] = vb.y;
            Bs[lc + 2][r] = vb.z; Bs[lc + 3][r] = vb.w;
        }
        __syncthreads();
#pragma unroll
        for (int k = 0; k < 16; k++) {
            float4 a0 = *(const float4*)&As[k][ty * 8];
            float4 a1 = *(const float4*)&As[k][ty * 8 + 4];
            float4 b0 = *(const float4*)&Bs[k][tx * 8];
            float4 b1 = *(const float4*)&Bs[k][tx * 8 + 4];
            float a[8] = {a0.x, a0.y, a0.z, a0.w, a1.x, a1.y, a1.z, a1.w};
            float b[8] = {b0.x, b0.y, b0.z, b0.w, b1.x, b1.y, b1.z, b1.w};
#pragma unroll
            for (int i = 0; i < 8; i++)
#pragma unroll
                for (int j = 0; j < 8; j++)
                    acc[i][j] = fmaf(a[i], b[j], acc[i][j]);
        }
        __syncthreads();
    }
}

__global__ __launch_bounds__(256) void uv_gemm(const float* __restrict__ X,
                                               const float* __restrict__ Uw,
                                               const float* __restrict__ Ub,
                                               const float* __restrict__ Vw,
                                               const float* __restrict__ Vb)
{
    const bool isV = (blockIdx.z == 1);
    const float* W    = isV ? Vw : Uw;
    const float* bias = isV ? Vb : Ub;
    float* Co         = isV ? g_v : g_u;
    const int m0 = blockIdx.y * 128, n0 = blockIdx.x * 128;
    float acc[8][8];
    gemm_core(X, W, CH, m0, n0, acc);
    const int tx = threadIdx.x & 15, ty = threadIdx.x >> 4;
#pragma unroll
    for (int i = 0; i < 8; i++) {
        int m = m0 + ty * 8 + i;
#pragma unroll
        for (int j = 0; j < 8; j += 4) {
            int n = n0 + tx * 8 + j;
            float4 o = make_float4(acc[i][j]     + bias[n],
                                   acc[i][j + 1] + bias[n + 1],
                                   acc[i][j + 2] + bias[n + 2],
                                   acc[i][j + 3] + bias[n + 3]);
            *(float4*)(Co + (size_t)m * CH + n) = o;
        }
    }
}

// ================= K4: sparse aggregate + per-row norm + relu =================
__global__ __launch_bounds__(128) void combine_kernel(const float* __restrict__ X)
{
    const int row = blockIdx.x, tid = threadIdx.x;
    __shared__ int   nidx[16];
    __shared__ float nw[16];
    __shared__ float red[128];
    __shared__ float mean_s, inv_s;

    const int   deg = g_deg[row];
    const float di  = g_dinv[row];
    if (tid < deg) {
        int j = g_idx[row * 16 + tid];
        nidx[tid] = j;
        nw[tid]   = di * g_dinv[j];
    }
    __syncthreads();

    float z[4];
#pragma unroll
    for (int q = 0; q < 4; q++) {
        int c = q * 128 + tid;
        float a = g_u[(size_t)row * CH + c];
        for (int t = 0; t < deg; t++)
            a = fmaf(nw[t], g_v[(size_t)nidx[t] * CH + c], a);
        z[q] = a;
    }

    red[tid] = z[0] + z[1] + z[2] + z[3];
    __syncthreads();
    for (int st = 64; st > 0; st >>= 1) { if (tid < st) red[tid] += red[tid + st]; __syncthreads(); }
    if (tid == 0) mean_s = red[0] * (1.f / CH);
    __syncthreads();
    const float mean = mean_s;

    float vs = 0.f;
#pragma unroll
    for (int q = 0; q < 4; q++) { float d = z[q] - mean; vs += d * d; }
    red[tid] = vs;
    __syncthreads();
    for (int st = 64; st > 0; st >>= 1) { if (tid < st) red[tid] += red[tid + st]; __syncthreads(); }
    if (tid == 0) inv_s = rsqrtf(red[0] * (1.f / CH) + EPSV);
    __syncthreads();
    const float inv = inv_s;

#pragma unroll
    for (int q = 0; q < 4; q++) {
        int c = q * 128 + tid;
        float h = X[(size_t)row * CH + c] + (z[q] - mean) * inv;
        g_h[(size_t)row * CH + c] = fmaxf(h, 0.f);
    }
}

// ================= K5: out = h @ fc_w^T + fc_b =================
__global__ __launch_bounds__(256) void fc_gemm(const float* __restrict__ Fw,
                                               const float* __restrict__ Fb,
                                               float* __restrict__ out)
{
    const int m0 = blockIdx.y * 128, n0 = blockIdx.x * 128;
    float acc[8][8];
    gemm_core(g_h, Fw, CH, m0, n0, acc);
    const int tx = threadIdx.x & 15, ty = threadIdx.x >> 4;
#pragma unroll
    for (int i = 0; i < 8; i++) {
        int m = m0 + ty * 8 + i;
#pragma unroll
        for (int j = 0; j < 8; j += 4) {
            int n = n0 + tx * 8 + j;
            float4 o = make_float4(acc[i][j]     + Fb[n],
                                   acc[i][j + 1] + Fb[n + 1],
                                   acc[i][j + 2] + Fb[n + 2],
                                   acc[i][j + 3] + Fb[n + 3]);
            *(float4*)(out + (size_t)m * OUTF + n) = o;
        }
    }
}

// ================= launch =================
extern "C" void kernel_launch(void* const* d_in, const int* in_sizes, int n_in,
                              void* d_out, int out_size)
{
    const float* x  = (const float*)d_in[0];
    const float* Uw = (const float*)d_in[1];
    const float* Ub = (const float*)d_in[2];
    const float* Vw = (const float*)d_in[3];
    const float* Vb = (const float*)d_in[4];
    const float* Fw = (const float*)d_in[5];
    const float* Fb = (const float*)d_in[6];
    float* out = (float*)d_out;

    si_mma<<<dim3(32, 32), 256>>>(x);            // bf16 tensor-core similarity (upper + mirror)
    topk_refine<<<NPTS, 256>>>(x);               // approx top-8 cands + fp32 exact top-4
    uv_gemm<<<dim3(4, 32, 2), 256>>>(x, Uw, Ub, Vw, Vb);
    combine_kernel<<<NPTS, 128>>>(x);
    fc_gemm<<<dim3(2, 32), 256>>>(Fw, Fb, out);
}

// round 4
// speedup vs baseline: 1.9243x; 1.2194x over previous
#include <cuda_runtime.h>
#include <cuda_bf16.h>
#include <cstdint>

#define NPTS 4096
#define CH   512
#define OUTF 256
#define EPSV 1e-5f
#define SA   40   // smem k-stride (bf16), padded to kill bank conflicts

// ---------------- scratch (device-side only; never referenced from host) ----------
__device__ __nv_bfloat16 g_sib[(size_t)NPTS * NPTS];  // 32 MB approx similarity
__device__ float g_u [(size_t)NPTS * CH];
__device__ float g_v [(size_t)NPTS * CH];
__device__ float g_h [(size_t)NPTS * CH];
__device__ float g_dinv[NPTS];
__device__ int   g_deg [NPTS];
__device__ int   g_idx [NPTS * 16];

__device__ __forceinline__ void mma16816(float c[4], const uint32_t a[4], const uint32_t b[2])
{
    asm volatile(
        "mma.sync.aligned.m16n8k16.row.col.f32.bf16.bf16.f32 "
        "{%0,%1,%2,%3}, {%4,%5,%6,%7}, {%8,%9}, {%0,%1,%2,%3};"
        : "+f"(c[0]), "+f"(c[1]), "+f"(c[2]), "+f"(c[3])
        : "r"(a[0]), "r"(a[1]), "r"(a[2]), "r"(a[3]), "r"(b[0]), "r"(b[1]));
}

// ================= K1: full si = x@x.T in bf16 tensor cores (coalesced stores) =====
__global__ __launch_bounds__(256) void si_mma(const float* __restrict__ X)
{
    const int m0 = blockIdx.y * 128, n0 = blockIdx.x * 128;

    __shared__ __nv_bfloat16 As[128 * SA];
    __shared__ __nv_bfloat16 Bs[128 * SA];

    const int tid  = threadIdx.x;
    const int warp = tid >> 5, lane = tid & 31;
    const int wm = warp & 3, wn = warp >> 2;
    const int grp = lane >> 2, qd = lane & 3;

    float acc[2][8][4];
#pragma unroll
    for (int mi = 0; mi < 2; mi++)
#pragma unroll
        for (int ni = 0; ni < 8; ni++)
#pragma unroll
            for (int e = 0; e < 4; e++) acc[mi][ni][e] = 0.f;

    const int lr = tid >> 3;
    const int lc = (tid & 7) * 4;

    for (int k0 = 0; k0 < CH; k0 += 32) {
#pragma unroll
        for (int p = 0; p < 4; p++) {
            int rr = lr + p * 32;
            float4 va = *(const float4*)(X + (size_t)(m0 + rr) * CH + k0 + lc);
            *(__nv_bfloat162*)&As[rr * SA + lc]     = __floats2bfloat162_rn(va.x, va.y);
            *(__nv_bfloat162*)&As[rr * SA + lc + 2] = __floats2bfloat162_rn(va.z, va.w);
            float4 vb = *(const float4*)(X + (size_t)(n0 + rr) * CH + k0 + lc);
            *(__nv_bfloat162*)&Bs[rr * SA + lc]     = __floats2bfloat162_rn(vb.x, vb.y);
            *(__nv_bfloat162*)&Bs[rr * SA + lc + 2] = __floats2bfloat162_rn(vb.z, vb.w);
        }
        __syncthreads();
#pragma unroll
        for (int kk = 0; kk < 32; kk += 16) {
            uint32_t afr[2][4], bfr[8][2];
#pragma unroll
            for (int mi = 0; mi < 2; mi++) {
                int row = wm * 32 + mi * 16 + grp;
                afr[mi][0] = *(const uint32_t*)&As[row * SA + kk + qd * 2];
                afr[mi][1] = *(const uint32_t*)&As[(row + 8) * SA + kk + qd * 2];
                afr[mi][2] = *(const uint32_t*)&As[row * SA + kk + qd * 2 + 8];
                afr[mi][3] = *(const uint32_t*)&As[(row + 8) * SA + kk + qd * 2 + 8];
            }
#pragma unroll
            for (int ni = 0; ni < 8; ni++) {
                int col = wn * 64 + ni * 8 + grp;
                bfr[ni][0] = *(const uint32_t*)&Bs[col * SA + kk + qd * 2];
                bfr[ni][1] = *(const uint32_t*)&Bs[col * SA + kk + qd * 2 + 8];
            }
#pragma unroll
            for (int mi = 0; mi < 2; mi++)
#pragma unroll
                for (int ni = 0; ni < 8; ni++)
                    mma16816(acc[mi][ni], afr[mi], bfr[ni]);
        }
        __syncthreads();
    }

#pragma unroll
    for (int mi = 0; mi < 2; mi++) {
        int m = m0 + wm * 32 + mi * 16 + grp;
#pragma unroll
        for (int ni = 0; ni < 8; ni++) {
            int n = n0 + wn * 64 + ni * 8 + qd * 2;
            *(__nv_bfloat162*)&g_sib[(size_t)m * NPTS + n] =
                __floats2bfloat162_rn(acc[mi][ni][0], acc[mi][ni][1]);
            *(__nv_bfloat162*)&g_sib[(size_t)(m + 8) * NPTS + n] =
                __floats2bfloat162_rn(acc[mi][ni][2], acc[mi][ni][3]);
        }
    }
}

// ================= K2: approx top-8 candidates + fp32 exact refine =================
__device__ __forceinline__ void ins8(float v[8], float x)
{
    if (x > v[7]) {
        v[7] = x;
#pragma unroll
        for (int i = 7; i > 0; i--) {
            if (v[i] > v[i - 1]) { float t = v[i]; v[i] = v[i - 1]; v[i - 1] = t; }
        }
    }
}

__global__ __launch_bounds__(256) void topk_refine(const float* __restrict__ X)
{
    const int row = blockIdx.x;
    const int tid = threadIdx.x;
    const int warp = tid >> 5, lane = tid & 31;
    const uint4* __restrict__ s4 = (const uint4*)(g_sib + (size_t)row * NPTS);

    __shared__ float sv[256][8];
    __shared__ float xr[CH];
    __shared__ float ex[32];
    __shared__ int   cand[32];
    __shared__ int   cnt;
    __shared__ float thr8_s;

    xr[tid]       = X[(size_t)row * CH + tid];
    xr[tid + 256] = X[(size_t)row * CH + tid + 256];
    if (tid == 0) cnt = 0;

    float v[8];
#pragma unroll
    for (int i = 0; i < 8; i++) v[i] = -1e30f;
#pragma unroll
    for (int q = 0; q < 2; q++) {
        uint4 u = s4[tid + q * 256];
        uint32_t w[4] = {u.x, u.y, u.z, u.w};
#pragma unroll
        for (int t = 0; t < 4; t++) {
            __nv_bfloat162 p = *(__nv_bfloat162*)&w[t];
            ins8(v, __bfloat162float(p.x));
            ins8(v, __bfloat162float(p.y));
        }
    }
#pragma unroll
    for (int i = 0; i < 8; i++) sv[tid][i] = v[i];
    __syncthreads();
    for (int st = 128; st > 0; st >>= 1) {
        if (tid < st) {
#pragma unroll
            for (int i = 0; i < 8; i++) ins8(v, sv[tid + st][i]);
#pragma unroll
            for (int i = 0; i < 8; i++) sv[tid][i] = v[i];
        }
        __syncthreads();
    }
    if (tid == 0) thr8_s = sv[0][7];
    __syncthreads();
    const float thr8 = thr8_s;

#pragma unroll
    for (int q = 0; q < 2; q++) {
        int jv = tid + q * 256;
        uint4 u = s4[jv];
        uint32_t w[4] = {u.x, u.y, u.z, u.w};
#pragma unroll
        for (int t = 0; t < 4; t++) {
            __nv_bfloat162 p = *(__nv_bfloat162*)&w[t];
            if (__bfloat162float(p.x) >= thr8) {
                int pi = atomicAdd(&cnt, 1);
                if (pi < 32) cand[pi] = jv * 8 + t * 2;
            }
            if (__bfloat162float(p.y) >= thr8) {
                int pi = atomicAdd(&cnt, 1);
                if (pi < 32) cand[pi] = jv * 8 + t * 2 + 1;
            }
        }
    }
    __syncthreads();
    const int cn = min(cnt, 32);

    for (int c = warp; c < cn; c += 8) {
        const float* __restrict__ xc = X + (size_t)cand[c] * CH;
        float sum = 0.f;
        for (int k = lane; k < CH; k += 32) sum = fmaf(xr[k], xc[k], sum);
#pragma unroll
        for (int o = 16; o > 0; o >>= 1) sum += __shfl_xor_sync(0xffffffffu, sum, o);
        if (lane == 0) ex[c] = sum;
    }
    __syncthreads();

    if (tid == 0) {
        float tmp[32];
        for (int c = 0; c < cn; c++) tmp[c] = ex[c];
        float thr = -1e30f;
        for (int p = 0; p < 4; p++) {
            int bidx = 0; float bv = -1e30f;
            for (int c = 0; c < cn; c++) if (tmp[c] > bv) { bv = tmp[c]; bidx = c; }
            thr = bv; tmp[bidx] = -1e30f;
        }
        int d = 0;
        for (int c = 0; c < cn; c++) {
            if (ex[c] >= thr) { if (d < 16) g_idx[row * 16 + d] = cand[c]; d++; }
        }
        g_deg[row]  = min(d, 16);
        g_dinv[row] = rsqrtf((float)d);
    }
}

// ============ split-bf16 tensor-core linear: Co = A @ W^T + bias ============
// mode 0: A = X param, Co = g_u   (ncols = CH)
// mode 1: A = X param, Co = g_v   (ncols = CH)
// mode 2: A = g_h,     Co = Cout  (ncols = OUTF)
// Device globals are resolved INSIDE the kernel (host cannot take their address).
__global__ __launch_bounds__(256) void lin_mma(const float* __restrict__ Ain,
                                               const float* __restrict__ W,
                                               const float* __restrict__ bias,
                                               float* __restrict__ Cout,
                                               int ncols, int mode)
{
    const float* __restrict__ A  = (mode == 2) ? (const float*)g_h : Ain;
    float* __restrict__ Co       = (mode == 0) ? g_u : (mode == 1) ? g_v : Cout;

    const int n0 = blockIdx.x * 128, m0 = blockIdx.y * 128;

    __shared__ __nv_bfloat16 Ah[128 * SA], Al[128 * SA];
    __shared__ __nv_bfloat16 Bh[128 * SA], Bl[128 * SA];

    const int tid  = threadIdx.x;
    const int warp = tid >> 5, lane = tid & 31;
    const int wm = warp & 3, wn = warp >> 2;
    const int grp = lane >> 2, qd = lane & 3;

    float acc[2][8][4];
#pragma unroll
    for (int mi = 0; mi < 2; mi++)
#pragma unroll
        for (int ni = 0; ni < 8; ni++)
#pragma unroll
            for (int e = 0; e < 4; e++) acc[mi][ni][e] = 0.f;

    const int lr = tid >> 3;
    const int lc = (tid & 7) * 4;

    for (int k0 = 0; k0 < CH; k0 += 32) {
#pragma unroll
        for (int p = 0; p < 4; p++) {
            int rr = lr + p * 32;
            float4 va = *(const float4*)(A + (size_t)(m0 + rr) * CH + k0 + lc);
            float4 vb = *(const float4*)(W + (size_t)(n0 + rr) * CH + k0 + lc);
            float fa[4] = {va.x, va.y, va.z, va.w};
            float fb[4] = {vb.x, vb.y, vb.z, vb.w};
#pragma unroll
            for (int t = 0; t < 4; t++) {
                __nv_bfloat16 h = __float2bfloat16_rn(fa[t]);
                Ah[rr * SA + lc + t] = h;
                Al[rr * SA + lc + t] = __float2bfloat16_rn(fa[t] - __bfloat162float(h));
                __nv_bfloat16 g = __float2bfloat16_rn(fb[t]);
                Bh[rr * SA + lc + t] = g;
                Bl[rr * SA + lc + t] = __float2bfloat16_rn(fb[t] - __bfloat162float(g));
            }
        }
        __syncthreads();
#pragma unroll
        for (int kk = 0; kk < 32; kk += 16) {
            uint32_t ah[2][4], al[2][4], bh[8][2], bl[8][2];
#pragma unroll
            for (int mi = 0; mi < 2; mi++) {
                int row = wm * 32 + mi * 16 + grp;
                ah[mi][0] = *(const uint32_t*)&Ah[row * SA + kk + qd * 2];
                ah[mi][1] = *(const uint32_t*)&Ah[(row + 8) * SA + kk + qd * 2];
                ah[mi][2] = *(const uint32_t*)&Ah[row * SA + kk + qd * 2 + 8];
                ah[mi][3] = *(const uint32_t*)&Ah[(row + 8) * SA + kk + qd * 2 + 8];
                al[mi][0] = *(const uint32_t*)&Al[row * SA + kk + qd * 2];
                al[mi][1] = *(const uint32_t*)&Al[(row + 8) * SA + kk + qd * 2];
                al[mi][2] = *(const uint32_t*)&Al[row * SA + kk + qd * 2 + 8];
                al[mi][3] = *(const uint32_t*)&Al[(row + 8) * SA + kk + qd * 2 + 8];
            }
#pragma unroll
            for (int ni = 0; ni < 8; ni++) {
                int col = wn * 64 + ni * 8 + grp;
                bh[ni][0] = *(const uint32_t*)&Bh[col * SA + kk + qd * 2];
                bh[ni][1] = *(const uint32_t*)&Bh[col * SA + kk + qd * 2 + 8];
                bl[ni][0] = *(const uint32_t*)&Bl[col * SA + kk + qd * 2];
                bl[ni][1] = *(const uint32_t*)&Bl[col * SA + kk + qd * 2 + 8];
            }
#pragma unroll
            for (int mi = 0; mi < 2; mi++)
#pragma unroll
                for (int ni = 0; ni < 8; ni++) {
                    mma16816(acc[mi][ni], ah[mi], bh[ni]);
                    mma16816(acc[mi][ni], ah[mi], bl[ni]);
                    mma16816(acc[mi][ni], al[mi], bh[ni]);
                }
        }
        __syncthreads();
    }

#pragma unroll
    for (int mi = 0; mi < 2; mi++) {
        int m = m0 + wm * 32 + mi * 16 + grp;
#pragma unroll
        for (int ni = 0; ni < 8; ni++) {
            int n = n0 + wn * 64 + ni * 8 + qd * 2;
            float b0 = bias[n], b1 = bias[n + 1];
            *(float2*)(Co + (size_t)m * ncols + n) =
                make_float2(acc[mi][ni][0] + b0, acc[mi][ni][1] + b1);
            *(float2*)(Co + (size_t)(m + 8) * ncols + n) =
                make_float2(acc[mi][ni][2] + b0, acc[mi][ni][3] + b1);
        }
    }
}

// ================= K4: sparse aggregate + per-row norm + relu =================
__global__ __launch_bounds__(128) void combine_kernel(const float* __restrict__ X)
{
    const int row = blockIdx.x, tid = threadIdx.x;
    __shared__ int   nidx[16];
    __shared__ float nw[16];
    __shared__ float red[128];
    __shared__ float mean_s, inv_s;

    const int   deg = g_deg[row];
    const float di  = g_dinv[row];
    if (tid < deg) {
        int j = g_idx[row * 16 + tid];
        nidx[tid] = j;
        nw[tid]   = di * g_dinv[j];
    }
    __syncthreads();

    float z[4];
#pragma unroll
    for (int q = 0; q < 4; q++) {
        int c = q * 128 + tid;
        float a = g_u[(size_t)row * CH + c];
        for (int t = 0; t < deg; t++)
            a = fmaf(nw[t], g_v[(size_t)nidx[t] * CH + c], a);
        z[q] = a;
    }

    red[tid] = z[0] + z[1] + z[2] + z[3];
    __syncthreads();
    for (int st = 64; st > 0; st >>= 1) { if (tid < st) red[tid] += red[tid + st]; __syncthreads(); }
    if (tid == 0) mean_s = red[0] * (1.f / CH);
    __syncthreads();
    const float mean = mean_s;

    float vs = 0.f;
#pragma unroll
    for (int q = 0; q < 4; q++) { float d = z[q] - mean; vs += d * d; }
    red[tid] = vs;
    __syncthreads();
    for (int st = 64; st > 0; st >>= 1) { if (tid < st) red[tid] += red[tid + st]; __syncthreads(); }
    if (tid == 0) inv_s = rsqrtf(red[0] * (1.f / CH) + EPSV);
    __syncthreads();
    const float inv = inv_s;

#pragma unroll
    for (int q = 0; q < 4; q++) {
        int c = q * 128 + tid;
        float h = X[(size_t)row * CH + c] + (z[q] - mean) * inv;
        g_h[(size_t)row * CH + c] = fmaxf(h, 0.f);
    }
}

// ================= launch =================
extern "C" void kernel_launch(void* const* d_in, const int* in_sizes, int n_in,
                              void* d_out, int out_size)
{
    const float* x  = (const float*)d_in[0];
    const float* Uw = (const float*)d_in[1];
    const float* Ub = (const float*)d_in[2];
    const float* Vw = (const float*)d_in[3];
    const float* Vb = (const float*)d_in[4];
    const float* Fw = (const float*)d_in[5];
    const float* Fb = (const float*)d_in[6];
    float* out = (float*)d_out;

    si_mma<<<dim3(32, 32), 256>>>(x);                          // full si, coalesced bf16 stores
    topk_refine<<<NPTS, 256>>>(x);                             // vectorized scan + exact refine
    lin_mma<<<dim3(4, 32), 256>>>(x, Uw, Ub, nullptr, CH, 0);  // u = x@Uw^T + Ub
    lin_mma<<<dim3(4, 32), 256>>>(x, Vw, Vb, nullptr, CH, 1);  // v = x@Vw^T + Vb
    combine_kernel<<<NPTS, 128>>>(x);                          // A@v + u, norm, relu
    lin_mma<<<dim3(2, 32), 256>>>(nullptr, Fw, Fb, out, OUTF, 2); // out = h@fc^T + fc_b
}

// round 5
// speedup vs baseline: 2.5724x; 1.3368x over previous
#include <cuda_runtime.h>
#include <cuda_bf16.h>
#include <cstdint>

#define NPTS 4096
#define CH   512
#define OUTF 256
#define EPSV 1e-5f
#define SA   40   // smem k-stride (bf16), padded to kill bank conflicts

// ---------------- scratch (device-side only) ----------------
__device__ __nv_bfloat16 g_sib[(size_t)NPTS * NPTS];  // 32 MB approx similarity
__device__ float g_u [(size_t)NPTS * CH];
__device__ float g_v [(size_t)NPTS * CH];
__device__ float g_h [(size_t)NPTS * CH];
__device__ float g_dinv[NPTS];
__device__ int   g_deg [NPTS];
__device__ int   g_idx [NPTS * 16];

__device__ __forceinline__ void mma16816(float c[4], const uint32_t a[4], const uint32_t b[2])
{
    asm volatile(
        "mma.sync.aligned.m16n8k16.row.col.f32.bf16.bf16.f32 "
        "{%0,%1,%2,%3}, {%4,%5,%6,%7}, {%8,%9}, {%0,%1,%2,%3};"
        : "+f"(c[0]), "+f"(c[1]), "+f"(c[2]), "+f"(c[3])
        : "r"(a[0]), "r"(a[1]), "r"(a[2]), "r"(a[3]), "r"(b[0]), "r"(b[1]));
}

// ===== K1: si = x@x.T, upper-triangular blocks; mirror staged via smem transpose =====
__global__ __launch_bounds__(256) void si_mma(const float* __restrict__ X)
{
    const int bj = blockIdx.x, bi = blockIdx.y;
    if (bi > bj) return;
    const int m0 = bi * 128, n0 = bj * 128;

    // aliased smem: [As | Bs] during MMA, Ts (transpose buffer) in epilogue
    __shared__ __align__(16) unsigned char sraw[128 * 136 * 2];  // 34816 B
    __nv_bfloat16* As = reinterpret_cast<__nv_bfloat16*>(sraw);
    __nv_bfloat16* Bs = As + 128 * SA;
    __nv_bfloat16* Ts = reinterpret_cast<__nv_bfloat16*>(sraw);

    const int tid  = threadIdx.x;
    const int warp = tid >> 5, lane = tid & 31;
    const int wm = warp & 3, wn = warp >> 2;
    const int grp = lane >> 2, qd = lane & 3;

    float acc[2][8][4];
#pragma unroll
    for (int mi = 0; mi < 2; mi++)
#pragma unroll
        for (int ni = 0; ni < 8; ni++)
#pragma unroll
            for (int e = 0; e < 4; e++) acc[mi][ni][e] = 0.f;

    const int lr = tid >> 3;
    const int lc = (tid & 7) * 4;

    for (int k0 = 0; k0 < CH; k0 += 32) {
#pragma unroll
        for (int p = 0; p < 4; p++) {
            int rr = lr + p * 32;
            float4 va = *(const float4*)(X + (size_t)(m0 + rr) * CH + k0 + lc);
            *(__nv_bfloat162*)&As[rr * SA + lc]     = __floats2bfloat162_rn(va.x, va.y);
            *(__nv_bfloat162*)&As[rr * SA + lc + 2] = __floats2bfloat162_rn(va.z, va.w);
            float4 vb = *(const float4*)(X + (size_t)(n0 + rr) * CH + k0 + lc);
            *(__nv_bfloat162*)&Bs[rr * SA + lc]     = __floats2bfloat162_rn(vb.x, vb.y);
            *(__nv_bfloat162*)&Bs[rr * SA + lc + 2] = __floats2bfloat162_rn(vb.z, vb.w);
        }
        __syncthreads();
#pragma unroll
        for (int kk = 0; kk < 32; kk += 16) {
            uint32_t afr[2][4], bfr[8][2];
#pragma unroll
            for (int mi = 0; mi < 2; mi++) {
                int row = wm * 32 + mi * 16 + grp;
                afr[mi][0] = *(const uint32_t*)&As[row * SA + kk + qd * 2];
                afr[mi][1] = *(const uint32_t*)&As[(row + 8) * SA + kk + qd * 2];
                afr[mi][2] = *(const uint32_t*)&As[row * SA + kk + qd * 2 + 8];
                afr[mi][3] = *(const uint32_t*)&As[(row + 8) * SA + kk + qd * 2 + 8];
            }
#pragma unroll
            for (int ni = 0; ni < 8; ni++) {
                int col = wn * 64 + ni * 8 + grp;
                bfr[ni][0] = *(const uint32_t*)&Bs[col * SA + kk + qd * 2];
                bfr[ni][1] = *(const uint32_t*)&Bs[col * SA + kk + qd * 2 + 8];
            }
#pragma unroll
            for (int mi = 0; mi < 2; mi++)
#pragma unroll
                for (int ni = 0; ni < 8; ni++)
                    mma16816(acc[mi][ni], afr[mi], bfr[ni]);
        }
        __syncthreads();
    }

    // normal coalesced store of (m0,n0) tile
#pragma unroll
    for (int mi = 0; mi < 2; mi++) {
        int m = m0 + wm * 32 + mi * 16 + grp;
#pragma unroll
        for (int ni = 0; ni < 8; ni++) {
            int n = n0 + wn * 64 + ni * 8 + qd * 2;
            *(__nv_bfloat162*)&g_sib[(size_t)m * NPTS + n] =
                __floats2bfloat162_rn(acc[mi][ni][0], acc[mi][ni][1]);
            *(__nv_bfloat162*)&g_sib[(size_t)(m + 8) * NPTS + n] =
                __floats2bfloat162_rn(acc[mi][ni][2], acc[mi][ni][3]);
        }
    }

    if (bi != bj) {
        // stage transposed tile in smem (Ts aliases As/Bs — MMA reads already fenced)
#pragma unroll
        for (int mi = 0; mi < 2; mi++) {
            int ml = wm * 32 + mi * 16 + grp;
#pragma unroll
            for (int ni = 0; ni < 8; ni++) {
                int nl = wn * 64 + ni * 8 + qd * 2;
                Ts[nl * 136 + ml]           = __float2bfloat16_rn(acc[mi][ni][0]);
                Ts[(nl + 1) * 136 + ml]     = __float2bfloat16_rn(acc[mi][ni][1]);
                Ts[nl * 136 + ml + 8]       = __float2bfloat16_rn(acc[mi][ni][2]);
                Ts[(nl + 1) * 136 + ml + 8] = __float2bfloat16_rn(acc[mi][ni][3]);
            }
        }
        __syncthreads();
        // coalesced 16B stores of the mirror tile at (n0, m0)
        const int r = tid >> 1, hh = (tid & 1) * 64;
#pragma unroll
        for (int i = 0; i < 8; i++) {
            *(uint4*)&g_sib[(size_t)(n0 + r) * NPTS + m0 + hh + i * 8] =
                *(const uint4*)&Ts[r * 136 + hh + i * 8];
        }
    }
}

// ================= K2: approx top-8 candidates + fp32 exact refine =================
__device__ __forceinline__ void ins8(float v[8], float x)
{
    if (x > v[7]) {
        v[7] = x;
#pragma unroll
        for (int i = 7; i > 0; i--) {
            if (v[i] > v[i - 1]) { float t = v[i]; v[i] = v[i - 1]; v[i - 1] = t; }
        }
    }
}

__global__ __launch_bounds__(256) void topk_refine(const float* __restrict__ X)
{
    const int row = blockIdx.x;
    const int tid = threadIdx.x;
    const int warp = tid >> 5, lane = tid & 31;
    const uint4* __restrict__ s4 = (const uint4*)(g_sib + (size_t)row * NPTS);

    __shared__ float sv[256][8];
    __shared__ float xr[CH];
    __shared__ float ex[32];
    __shared__ int   cand[32];
    __shared__ int   cnt;
    __shared__ float thr8_s;

    xr[tid]       = X[(size_t)row * CH + tid];
    xr[tid + 256] = X[(size_t)row * CH + tid + 256];
    if (tid == 0) cnt = 0;

    float v[8];
#pragma unroll
    for (int i = 0; i < 8; i++) v[i] = -1e30f;
#pragma unroll
    for (int q = 0; q < 2; q++) {
        uint4 u = s4[tid + q * 256];
        uint32_t w[4] = {u.x, u.y, u.z, u.w};
#pragma unroll
        for (int t = 0; t < 4; t++) {
            __nv_bfloat162 p = *(__nv_bfloat162*)&w[t];
            ins8(v, __bfloat162float(p.x));
            ins8(v, __bfloat162float(p.y));
        }
    }
#pragma unroll
    for (int i = 0; i < 8; i++) sv[tid][i] = v[i];
    __syncthreads();
    for (int st = 128; st > 0; st >>= 1) {
        if (tid < st) {
#pragma unroll
            for (int i = 0; i < 8; i++) ins8(v, sv[tid + st][i]);
#pragma unroll
            for (int i = 0; i < 8; i++) sv[tid][i] = v[i];
        }
        __syncthreads();
    }
    if (tid == 0) thr8_s = sv[0][7];
    __syncthreads();
    const float thr8 = thr8_s;

#pragma unroll
    for (int q = 0; q < 2; q++) {
        int jv = tid + q * 256;
        uint4 u = s4[jv];
        uint32_t w[4] = {u.x, u.y, u.z, u.w};
#pragma unroll
        for (int t = 0; t < 4; t++) {
            __nv_bfloat162 p = *(__nv_bfloat162*)&w[t];
            if (__bfloat162float(p.x) >= thr8) {
                int pi = atomicAdd(&cnt, 1);
                if (pi < 32) cand[pi] = jv * 8 + t * 2;
            }
            if (__bfloat162float(p.y) >= thr8) {
                int pi = atomicAdd(&cnt, 1);
                if (pi < 32) cand[pi] = jv * 8 + t * 2 + 1;
            }
        }
    }
    __syncthreads();
    const int cn = min(cnt, 32);

    for (int c = warp; c < cn; c += 8) {
        const float* __restrict__ xc = X + (size_t)cand[c] * CH;
        float sum = 0.f;
        for (int k = lane; k < CH; k += 32) sum = fmaf(xr[k], xc[k], sum);
#pragma unroll
        for (int o = 16; o > 0; o >>= 1) sum += __shfl_xor_sync(0xffffffffu, sum, o);
        if (lane == 0) ex[c] = sum;
    }
    __syncthreads();

    if (tid == 0) {
        float tmp[32];
        for (int c = 0; c < cn; c++) tmp[c] = ex[c];
        float thr = -1e30f;
        for (int p = 0; p < 4; p++) {
            int bidx = 0; float bv = -1e30f;
            for (int c = 0; c < cn; c++) if (tmp[c] > bv) { bv = tmp[c]; bidx = c; }
            thr = bv; tmp[bidx] = -1e30f;
        }
        int d = 0;
        for (int c = 0; c < cn; c++) {
            if (ex[c] >= thr) { if (d < 16) g_idx[row * 16 + d] = cand[c]; d++; }
        }
        g_deg[row]  = min(d, 16);
        g_dinv[row] = rsqrtf((float)d);
    }
}

// ======== split-bf16 tensor-core linear, templated M-tile (64*MI rows) ========
// mode 0 (MI=2): fused U/V — blockIdx.z selects Wa/Wb, output g_u/g_v, A = Ain (x)
// mode 2 (MI=1): fc — A = g_h, W = Wa, bias = ba, output Cout
template <int MI>
__global__ __launch_bounds__(256) void lin_mma(const float* __restrict__ Ain,
                                               const float* __restrict__ Wa,
                                               const float* __restrict__ ba,
                                               const float* __restrict__ Wb,
                                               const float* __restrict__ bb,
                                               float* __restrict__ Cout,
                                               int ncols, int mode)
{
    const bool z1 = (mode == 0) && (blockIdx.z == 1);
    const float* __restrict__ A    = (mode == 2) ? (const float*)g_h : Ain;
    const float* __restrict__ W    = z1 ? Wb : Wa;
    const float* __restrict__ bias = z1 ? bb : ba;
    float* __restrict__ Co = (mode == 0) ? (z1 ? g_v : g_u) : Cout;

    const int n0 = blockIdx.x * 128, m0 = blockIdx.y * (64 * MI);

    __shared__ __nv_bfloat16 Ah[64 * MI * SA], Al[64 * MI * SA];
    __shared__ __nv_bfloat16 Bh[128 * SA],     Bl[128 * SA];

    const int tid  = threadIdx.x;
    const int warp = tid >> 5, lane = tid & 31;
    const int wm = warp & 3, wn = warp >> 2;
    const int grp = lane >> 2, qd = lane & 3;

    float acc[MI][8][4];
#pragma unroll
    for (int mi = 0; mi < MI; mi++)
#pragma unroll
        for (int ni = 0; ni < 8; ni++)
#pragma unroll
            for (int e = 0; e < 4; e++) acc[mi][ni][e] = 0.f;

    const int lr = tid >> 3;
    const int lc = (tid & 7) * 4;

    for (int k0 = 0; k0 < CH; k0 += 32) {
#pragma unroll
        for (int p = 0; p < 2 * MI; p++) {
            int rr = lr + p * 32;
            float4 va = *(const float4*)(A + (size_t)(m0 + rr) * CH + k0 + lc);
            __nv_bfloat162 h01 = __floats2bfloat162_rn(va.x, va.y);
            __nv_bfloat162 h23 = __floats2bfloat162_rn(va.z, va.w);
            *(__nv_bfloat162*)&Ah[rr * SA + lc]     = h01;
            *(__nv_bfloat162*)&Ah[rr * SA + lc + 2] = h23;
            *(__nv_bfloat162*)&Al[rr * SA + lc] =
                __floats2bfloat162_rn(va.x - __bfloat162float(h01.x),
                                      va.y - __bfloat162float(h01.y));
            *(__nv_bfloat162*)&Al[rr * SA + lc + 2] =
                __floats2bfloat162_rn(va.z - __bfloat162float(h23.x),
                                      va.w - __bfloat162float(h23.y));
        }
#pragma unroll
        for (int p = 0; p < 4; p++) {
            int rr = lr + p * 32;
            float4 vb = *(const float4*)(W + (size_t)(n0 + rr) * CH + k0 + lc);
            __nv_bfloat162 h01 = __floats2bfloat162_rn(vb.x, vb.y);
            __nv_bfloat162 h23 = __floats2bfloat162_rn(vb.z, vb.w);
            *(__nv_bfloat162*)&Bh[rr * SA + lc]     = h01;
            *(__nv_bfloat162*)&Bh[rr * SA + lc + 2] = h23;
            *(__nv_bfloat162*)&Bl[rr * SA + lc] =
                __floats2bfloat162_rn(vb.x - __bfloat162float(h01.x),
                                      vb.y - __bfloat162float(h01.y));
            *(__nv_bfloat162*)&Bl[rr * SA + lc + 2] =
                __floats2bfloat162_rn(vb.z - __bfloat162float(h23.x),
                                      vb.w - __bfloat162float(h23.y));
        }
        __syncthreads();
#pragma unroll
        for (int kk = 0; kk < 32; kk += 16) {
            uint32_t ah[MI][4], al[MI][4], bh[8][2], bl[8][2];
#pragma unroll
            for (int mi = 0; mi < MI; mi++) {
                int row = wm * (16 * MI) + mi * 16 + grp;
                ah[mi][0] = *(const uint32_t*)&Ah[row * SA + kk + qd * 2];
                ah[mi][1] = *(const uint32_t*)&Ah[(row + 8) * SA + kk + qd * 2];
                ah[mi][2] = *(const uint32_t*)&Ah[row * SA + kk + qd * 2 + 8];
                ah[mi][3] = *(const uint32_t*)&Ah[(row + 8) * SA + kk + qd * 2 + 8];
                al[mi][0] = *(const uint32_t*)&Al[row * SA + kk + qd * 2];
                al[mi][1] = *(const uint32_t*)&Al[(row + 8) * SA + kk + qd * 2];
                al[mi][2] = *(const uint32_t*)&Al[row * SA + kk + qd * 2 + 8];
                al[mi][3] = *(const uint32_t*)&Al[(row + 8) * SA + kk + qd * 2 + 8];
            }
#pragma unroll
            for (int ni = 0; ni < 8; ni++) {
                int col = wn * 64 + ni * 8 + grp;
                bh[ni][0] = *(const uint32_t*)&Bh[col * SA + kk + qd * 2];
                bh[ni][1] = *(const uint32_t*)&Bh[col * SA + kk + qd * 2 + 8];
                bl[ni][0] = *(const uint32_t*)&Bl[col * SA + kk + qd * 2];
                bl[ni][1] = *(const uint32_t*)&Bl[col * SA + kk + qd * 2 + 8];
            }
#pragma unroll
            for (int mi = 0; mi < MI; mi++)
#pragma unroll
                for (int ni = 0; ni < 8; ni++) {
                    mma16816(acc[mi][ni], ah[mi], bh[ni]);
                    mma16816(acc[mi][ni], ah[mi], bl[ni]);
                    mma16816(acc[mi][ni], al[mi], bh[ni]);
                }
        }
        __syncthreads();
    }

#pragma unroll
    for (int mi = 0; mi < MI; mi++) {
        int m = m0 + wm * (16 * MI) + mi * 16 + grp;
#pragma unroll
        for (int ni = 0; ni < 8; ni++) {
            int n = n0 + wn * 64 + ni * 8 + qd * 2;
            float b0 = bias[n], b1 = bias[n + 1];
            *(float2*)(Co + (size_t)m * ncols + n) =
                make_float2(acc[mi][ni][0] + b0, acc[mi][ni][1] + b1);
            *(float2*)(Co + (size_t)(m + 8) * ncols + n) =
                make_float2(acc[mi][ni][2] + b0, acc[mi][ni][3] + b1);
        }
    }
}

// ================= K4: sparse aggregate + per-row norm + relu =================
__global__ __launch_bounds__(128) void combine_kernel(const float* __restrict__ X)
{
    const int row = blockIdx.x, tid = threadIdx.x;
    __shared__ int   nidx[16];
    __shared__ float nw[16];
    __shared__ float red[128];
    __shared__ float mean_s, inv_s;

    const int   deg = g_deg[row];
    const float di  = g_dinv[row];
    if (tid < deg) {
        int j = g_idx[row * 16 + tid];
        nidx[tid] = j;
        nw[tid]   = di * g_dinv[j];
    }
    __syncthreads();

    float z[4];
#pragma unroll
    for (int q = 0; q < 4; q++) {
        int c = q * 128 + tid;
        float a = g_u[(size_t)row * CH + c];
        for (int t = 0; t < deg; t++)
            a = fmaf(nw[t], g_v[(size_t)nidx[t] * CH + c], a);
        z[q] = a;
    }

    red[tid] = z[0] + z[1] + z[2] + z[3];
    __syncthreads();
    for (int st = 64; st > 0; st >>= 1) { if (tid < st) red[tid] += red[tid + st]; __syncthreads(); }
    if (tid == 0) mean_s = red[0] * (1.f / CH);
    __syncthreads();
    const float mean = mean_s;

    float vs = 0.f;
#pragma unroll
    for (int q = 0; q < 4; q++) { float d = z[q] - mean; vs += d * d; }
    red[tid] = vs;
    __syncthreads();
    for (int st = 64; st > 0; st >>= 1) { if (tid < st) red[tid] += red[tid + st]; __syncthreads(); }
    if (tid == 0) inv_s = rsqrtf(red[0] * (1.f / CH) + EPSV);
    __syncthreads();
    const float inv = inv_s;

#pragma unroll
    for (int q = 0; q < 4; q++) {
        int c = q * 128 + tid;
        float h = X[(size_t)row * CH + c] + (z[q] - mean) * inv;
        g_h[(size_t)row * CH + c] = fmaxf(h, 0.f);
    }
}

// ================= launch =================
extern "C" void kernel_launch(void* const* d_in, const int* in_sizes, int n_in,
                              void* d_out, int out_size)
{
    const float* x  = (const float*)d_in[0];
    const float* Uw = (const float*)d_in[1];
    const float* Ub = (const float*)d_in[2];
    const float* Vw = (const float*)d_in[3];
    const float* Vb = (const float*)d_in[4];
    const float* Fw = (const float*)d_in[5];
    const float* Fb = (const float*)d_in[6];
    float* out = (float*)d_out;

    si_mma<<<dim3(32, 32), 256>>>(x);                 // triangular si + coalesced mirror
    topk_refine<<<NPTS, 256>>>(x);                    // approx top-8 + fp32 exact top-4
    lin_mma<2><<<dim3(4, 32, 2), 256>>>(x, Uw, Ub, Vw, Vb, nullptr, CH, 0);  // fused u,v
    combine_kernel<<<NPTS, 128>>>(x);                 // A@v + u, norm, relu
    lin_mma<1><<<dim3(2, 64, 1), 256>>>(nullptr, Fw, Fb, nullptr, nullptr, out, OUTF, 2); // fc
}